// round 1
// baseline (speedup 1.0000x reference)
#include <cuda_runtime.h>
#include <math.h>

#define N_NODES 50000
#define N_EDGES 500000
#define IN_DIM  384
#define HID     128
#define NHEAD   8
#define CH      16
#define NLAYER  3
#define OUT_DIM 16

// ---------------- device scratch (static: no allocation) ----------------
__device__ int   g_rowptr[N_NODES + 1];
__device__ int   g_cursor[N_NODES];
__device__ int   g_col[N_EDGES];
__device__ int   g_bsums[64];
__device__ float g_h[(size_t)N_NODES * HID];
__device__ float g_xh[(size_t)N_NODES * HID];
__device__ float g_als[N_NODES * NHEAD];
__device__ float g_ald[N_NODES * NHEAD];

// ---------------- CSR build ----------------
__global__ void zero_rowptr_kernel() {
    int i = blockIdx.x * blockDim.x + threadIdx.x;
    if (i <= N_NODES) g_rowptr[i] = 0;
}

__global__ void hist_kernel(const int* __restrict__ dst) {
    int i = blockIdx.x * blockDim.x + threadIdx.x;
    if (i < N_EDGES) atomicAdd(&g_rowptr[dst[i] + 1], 1);
}

// inclusive scan over g_rowptr[0..N_NODES], 1024 elems per block
__global__ void scan_block_kernel() {
    __shared__ int s[1024];
    const int n = N_NODES + 1;
    int t = threadIdx.x;
    int gid = blockIdx.x * 1024 + t;
    s[t] = (gid < n) ? g_rowptr[gid] : 0;
    __syncthreads();
    #pragma unroll
    for (int off = 1; off < 1024; off <<= 1) {
        int v = (t >= off) ? s[t - off] : 0;
        __syncthreads();
        s[t] += v;
        __syncthreads();
    }
    if (gid < n) g_rowptr[gid] = s[t];
    if (t == 1023) g_bsums[blockIdx.x] = s[1023];
}

__global__ void scan_sums_kernel(int nb) {
    // single thread: exclusive scan of block sums
    int acc = 0;
    for (int i = 0; i < nb; ++i) {
        int v = g_bsums[i];
        g_bsums[i] = acc;
        acc += v;
    }
}

__global__ void scan_add_kernel() {
    const int n = N_NODES + 1;
    int gid = blockIdx.x * 1024 + threadIdx.x;
    if (gid < n) {
        int v = g_rowptr[gid] + g_bsums[blockIdx.x];
        g_rowptr[gid] = v;
        if (gid < N_NODES) g_cursor[gid] = v;
    }
}

__global__ void scatter_kernel(const int* __restrict__ src, const int* __restrict__ dst) {
    int i = blockIdx.x * blockDim.x + threadIdx.x;
    if (i < N_EDGES) {
        int d = dst[i];
        int pos = atomicAdd(&g_cursor[d], 1);
        g_col[pos] = src[i];
    }
}

// ---------------- fp32 SIMT GEMM: C[M,128] = A[M,K] @ B[K,128] ----------------
// BM=128, BN=128, BK=8, 256 threads, 8x8 per-thread tile
template<bool BIAS_RELU>
__global__ __launch_bounds__(256)
void gemm_f32(const float* __restrict__ A, const float* __restrict__ B,
              const float* __restrict__ bias, float* __restrict__ C,
              int M, int K)
{
    __shared__ __align__(16) float As[8][128];
    __shared__ __align__(16) float Bs[8][128];
    const int tid = threadIdx.x;
    const int tx = tid & 15, ty = tid >> 4;
    const int m0 = blockIdx.x * 128;
    const int arow = tid >> 1, akq = (tid & 1) * 4;
    const int brow = tid >> 5, bcol = (tid & 31) * 4;
    const int r0 = ty * 4, r1 = r0 + 64, c0 = tx * 4, c1 = c0 + 64;

    float acc[8][8];
    #pragma unroll
    for (int i = 0; i < 8; ++i)
        #pragma unroll
        for (int j = 0; j < 8; ++j) acc[i][j] = 0.f;

    const int gmA = m0 + arow;
    const bool aval = (gmA < M);
    const float* Aptr = A + (size_t)gmA * K + akq;

    for (int k0 = 0; k0 < K; k0 += 8) {
        float4 av = aval ? *(const float4*)(Aptr + k0) : make_float4(0.f, 0.f, 0.f, 0.f);
        As[akq + 0][arow] = av.x;
        As[akq + 1][arow] = av.y;
        As[akq + 2][arow] = av.z;
        As[akq + 3][arow] = av.w;
        float4 bv = *(const float4*)&B[(size_t)(k0 + brow) * HID + bcol];
        *(float4*)&Bs[brow][bcol] = bv;
        __syncthreads();
        #pragma unroll
        for (int k = 0; k < 8; ++k) {
            float4 a0 = *(const float4*)&As[k][r0];
            float4 a1 = *(const float4*)&As[k][r1];
            float4 b0 = *(const float4*)&Bs[k][c0];
            float4 b1 = *(const float4*)&Bs[k][c1];
            float ar[8] = {a0.x, a0.y, a0.z, a0.w, a1.x, a1.y, a1.z, a1.w};
            float br[8] = {b0.x, b0.y, b0.z, b0.w, b1.x, b1.y, b1.z, b1.w};
            #pragma unroll
            for (int i = 0; i < 8; ++i)
                #pragma unroll
                for (int j = 0; j < 8; ++j)
                    acc[i][j] = fmaf(ar[i], br[j], acc[i][j]);
        }
        __syncthreads();
    }

    #pragma unroll
    for (int i = 0; i < 8; ++i) {
        int row = m0 + ((i < 4) ? (r0 + i) : (r1 + i - 4));
        if (row >= M) continue;
        float4 v0, v1;
        v0.x = acc[i][0]; v0.y = acc[i][1]; v0.z = acc[i][2]; v0.w = acc[i][3];
        v1.x = acc[i][4]; v1.y = acc[i][5]; v1.z = acc[i][6]; v1.w = acc[i][7];
        if (BIAS_RELU) {
            v0.x = fmaxf(v0.x + bias[c0 + 0], 0.f);
            v0.y = fmaxf(v0.y + bias[c0 + 1], 0.f);
            v0.z = fmaxf(v0.z + bias[c0 + 2], 0.f);
            v0.w = fmaxf(v0.w + bias[c0 + 3], 0.f);
            v1.x = fmaxf(v1.x + bias[c1 + 0], 0.f);
            v1.y = fmaxf(v1.y + bias[c1 + 1], 0.f);
            v1.z = fmaxf(v1.z + bias[c1 + 2], 0.f);
            v1.w = fmaxf(v1.w + bias[c1 + 3], 0.f);
        }
        *(float4*)&C[(size_t)row * HID + c0] = v0;
        *(float4*)&C[(size_t)row * HID + c1] = v1;
    }
}

// ---------------- per-(node,head) attention logits ----------------
__global__ void al_kernel(const float* __restrict__ xh,
                          const float* __restrict__ att_s,
                          const float* __restrict__ att_d)
{
    int idx = blockIdx.x * blockDim.x + threadIdx.x;
    if (idx >= N_NODES * NHEAD) return;
    int n = idx >> 3, hd = idx & 7;
    const float* xp = xh + (size_t)n * HID + hd * CH;
    const float* as = att_s + hd * CH;
    const float* ad = att_d + hd * CH;
    float ss = 0.f, dd = 0.f;
    #pragma unroll
    for (int c = 0; c < CH; c += 4) {
        float4 v = *(const float4*)(xp + c);
        float4 a = *(const float4*)(as + c);
        float4 b = *(const float4*)(ad + c);
        ss += v.x * a.x + v.y * a.y + v.z * a.z + v.w * a.w;
        dd += v.x * b.x + v.y * b.y + v.z * b.z + v.w * b.w;
    }
    g_als[idx] = ss;
    g_ald[idx] = dd;
}

// ---------------- GAT aggregation: warp per dst node ----------------
// online softmax over incoming edges (+ implicit self-loop), then
// fused: +gat_b, +residual(h), layernorm, relu, in-place h update.
__global__ __launch_bounds__(256)
void gat_aggregate(const float* __restrict__ xh,
                   const float* __restrict__ gat_b,
                   const float* __restrict__ ln_g,
                   const float* __restrict__ ln_b,
                   float* __restrict__ h)
{
    int w = (blockIdx.x * blockDim.x + threadIdx.x) >> 5;
    if (w >= N_NODES) return;
    int lane = threadIdx.x & 31;
    int hd = lane >> 2;          // head for this lane's 4 features
    int f = lane * 4;            // feature base

    float a_d = g_ald[w * NHEAD + hd];
    // self-loop seeds the online softmax
    float e0 = g_als[w * NHEAD + hd] + a_d;
    e0 = fmaxf(e0, 0.2f * e0);   // leaky_relu(x) == max(x, 0.2x)
    float m = e0;
    float denom = 1.0f;
    float4 acc = *(const float4*)&xh[(size_t)w * HID + f];

    int beg = g_rowptr[w], end = g_rowptr[w + 1];
    for (int i = beg; i < end; ++i) {
        int s = g_col[i];
        float e2 = g_als[s * NHEAD + hd] + a_d;
        e2 = fmaxf(e2, 0.2f * e2);
        float mn = fmaxf(m, e2);
        float sc = __expf(m - mn);
        float p  = __expf(e2 - mn);
        float4 v = *(const float4*)&xh[(size_t)s * HID + f];
        acc.x = acc.x * sc + p * v.x;
        acc.y = acc.y * sc + p * v.y;
        acc.z = acc.z * sc + p * v.z;
        acc.w = acc.w * sc + p * v.w;
        denom = denom * sc + p;
        m = mn;
    }

    float inv = 1.0f / denom;
    float4 r  = *(const float4*)&h[(size_t)w * HID + f];
    float4 gb = *(const float4*)&gat_b[f];
    float v0 = fmaf(acc.x, inv, gb.x + r.x);
    float v1 = fmaf(acc.y, inv, gb.y + r.y);
    float v2 = fmaf(acc.z, inv, gb.z + r.z);
    float v3 = fmaf(acc.w, inv, gb.w + r.w);

    float sum = v0 + v1 + v2 + v3;
    float sq  = v0 * v0 + v1 * v1 + v2 * v2 + v3 * v3;
    #pragma unroll
    for (int off = 16; off; off >>= 1) {
        sum += __shfl_xor_sync(0xffffffffu, sum, off);
        sq  += __shfl_xor_sync(0xffffffffu, sq,  off);
    }
    float mean = sum * (1.0f / 128.0f);
    float var  = sq  * (1.0f / 128.0f) - mean * mean;
    float rs = rsqrtf(var + 1e-5f);

    float4 g4 = *(const float4*)&ln_g[f];
    float4 b4 = *(const float4*)&ln_b[f];
    float4 o;
    o.x = fmaxf((v0 - mean) * rs * g4.x + b4.x, 0.f);
    o.y = fmaxf((v1 - mean) * rs * g4.y + b4.y, 0.f);
    o.z = fmaxf((v2 - mean) * rs * g4.z + b4.z, 0.f);
    o.w = fmaxf((v3 - mean) * rs * g4.w + b4.w, 0.f);
    *(float4*)&h[(size_t)w * HID + f] = o;
}

// ---------------- classifier + log_softmax (fused) ----------------
__global__ __launch_bounds__(256)
void classifier_kernel(const float* __restrict__ h,
                       const float* __restrict__ w1, const float* __restrict__ b1,
                       const float* __restrict__ w2, const float* __restrict__ b2,
                       float* __restrict__ out)
{
    __shared__ __align__(16) float s_w1[HID * 64];
    __shared__ __align__(16) float s_w2[64 * OUT_DIM];
    __shared__ float s_b1[64];
    __shared__ float s_b2[OUT_DIM];
    __shared__ __align__(16) float s_h[8][HID];
    __shared__ float s_hid[8][64];

    int tid = threadIdx.x;
    for (int i = tid; i < HID * 64; i += 256) s_w1[i] = w1[i];
    for (int i = tid; i < 64 * OUT_DIM; i += 256) s_w2[i] = w2[i];
    if (tid < 64) s_b1[tid] = b1[tid];
    if (tid < OUT_DIM) s_b2[tid] = b2[tid];
    __syncthreads();

    int warp = tid >> 5, lane = tid & 31;
    int stride = gridDim.x * 8;
    for (int row = blockIdx.x * 8 + warp; row < N_NODES; row += stride) {
        *(float4*)&s_h[warp][lane * 4] = *(const float4*)&h[(size_t)row * HID + lane * 4];
        __syncwarp();
        // hidden layer: lane computes outputs (lane) and (lane+32)
        float acc0 = 0.f, acc1 = 0.f;
        #pragma unroll 8
        for (int k = 0; k < HID; ++k) {
            float x = s_h[warp][k];
            acc0 = fmaf(x, s_w1[k * 64 + lane], acc0);
            acc1 = fmaf(x, s_w1[k * 64 + lane + 32], acc1);
        }
        acc0 = fmaxf(acc0 + s_b1[lane], 0.f);
        acc1 = fmaxf(acc1 + s_b1[lane + 32], 0.f);
        s_hid[warp][lane] = acc0;
        s_hid[warp][lane + 32] = acc1;
        __syncwarp();
        // logits: split-K across lane halves
        int o = lane & 15;
        int kbase = (lane >> 4) * 32;
        float part = 0.f;
        #pragma unroll 8
        for (int k = 0; k < 32; ++k)
            part = fmaf(s_hid[warp][kbase + k], s_w2[(kbase + k) * OUT_DIM + o], part);
        part += __shfl_xor_sync(0xffffffffu, part, 16);
        float logit = part + s_b2[o];
        // log_softmax over 16 classes (both half-warps hold identical copies)
        float mx = logit;
        #pragma unroll
        for (int off = 8; off; off >>= 1)
            mx = fmaxf(mx, __shfl_xor_sync(0xffffffffu, mx, off));
        float ex = __expf(logit - mx);
        float sm = ex;
        #pragma unroll
        for (int off = 8; off; off >>= 1)
            sm += __shfl_xor_sync(0xffffffffu, sm, off);
        float res = logit - mx - logf(sm);
        if (lane < 16) out[(size_t)row * OUT_DIM + lane] = res;
        __syncwarp();
    }
}

// ---------------- launch ----------------
extern "C" void kernel_launch(void* const* d_in, const int* in_sizes, int n_in,
                              void* d_out, int out_size)
{
    const float* x       = (const float*)d_in[0];
    const int*   ei      = (const int*)  d_in[1];
    const float* proj_w  = (const float*)d_in[2];
    const float* proj_b  = (const float*)d_in[3];
    const float* lin_w   = (const float*)d_in[4];
    const float* att_src = (const float*)d_in[5];
    const float* att_dst = (const float*)d_in[6];
    const float* gat_b   = (const float*)d_in[7];
    const float* ln_g    = (const float*)d_in[8];
    const float* ln_b    = (const float*)d_in[9];
    const float* cls_w1  = (const float*)d_in[10];
    const float* cls_b1  = (const float*)d_in[11];
    const float* cls_w2  = (const float*)d_in[12];
    const float* cls_b2  = (const float*)d_in[13];
    float* out = (float*)d_out;

    const int* src = ei;
    const int* dst = ei + N_EDGES;

    float *h_ptr = nullptr, *xh_ptr = nullptr;
    cudaGetSymbolAddress((void**)&h_ptr, g_h);
    cudaGetSymbolAddress((void**)&xh_ptr, g_xh);

    const int SCAN_BLOCKS = (N_NODES + 1 + 1023) / 1024;  // 49

    // --- CSR build (once; graph is static across layers) ---
    zero_rowptr_kernel<<<(N_NODES + 1 + 255) / 256, 256>>>();
    hist_kernel<<<(N_EDGES + 255) / 256, 256>>>(dst);
    scan_block_kernel<<<SCAN_BLOCKS, 1024>>>();
    scan_sums_kernel<<<1, 1>>>(SCAN_BLOCKS);
    scan_add_kernel<<<SCAN_BLOCKS, 1024>>>();
    scatter_kernel<<<(N_EDGES + 255) / 256, 256>>>(src, dst);

    const int GEMM_GRID = (N_NODES + 127) / 128;  // 391

    // --- projection: h = relu(x @ proj_w + proj_b) ---
    gemm_f32<true><<<GEMM_GRID, 256>>>(x, proj_w, proj_b, h_ptr, N_NODES, IN_DIM);

    // --- GAT layers ---
    for (int l = 0; l < NLAYER; ++l) {
        gemm_f32<false><<<GEMM_GRID, 256>>>(h_ptr, lin_w + (size_t)l * HID * HID,
                                            nullptr, xh_ptr, N_NODES, HID);
        al_kernel<<<(N_NODES * NHEAD + 255) / 256, 256>>>(
            xh_ptr, att_src + l * NHEAD * CH, att_dst + l * NHEAD * CH);
        gat_aggregate<<<N_NODES / 8, 256>>>(
            xh_ptr, gat_b + l * HID, ln_g + l * HID, ln_b + l * HID, h_ptr);
    }

    // --- classifier + log_softmax ---
    classifier_kernel<<<592, 256>>>(h_ptr, cls_w1, cls_b1, cls_w2, cls_b2, out);
}

// round 4
// speedup vs baseline: 1.3953x; 1.3953x over previous
#include <cuda_runtime.h>
#include <cuda_bf16.h>
#include <math.h>
#include <stdint.h>

#define N_NODES 50000
#define N_EDGES 500000
#define IN_DIM  384
#define HID     128
#define NHEAD   8
#define CH      16
#define NLAYER  3
#define OUT_DIM 16

// ================= device scratch =================
__device__ int   g_rowptr[N_NODES + 1];
__device__ int   g_cursor[N_NODES];
__device__ int   g_col[N_EDGES];
__device__ int   g_bsums[64];
__device__ float g_h[(size_t)N_NODES * HID];
__device__ float g_xh[(size_t)N_NODES * HID];
__device__ float g_als[N_NODES * NHEAD];
__device__ float g_ald[N_NODES * NHEAD];
// pre-split weights, K-major [128][K]: proj (K=384) at 0, lin[l] (K=128) after
#define B_PROJ_OFF 0
#define B_LIN_OFF  (128 * IN_DIM)
__device__ __nv_bfloat16 g_bhi[128 * IN_DIM + NLAYER * 128 * HID];
__device__ __nv_bfloat16 g_blo[128 * IN_DIM + NLAYER * 128 * HID];

// ================= CSR build =================
__global__ void zero_rowptr_kernel() {
    int i = blockIdx.x * blockDim.x + threadIdx.x;
    if (i <= N_NODES) g_rowptr[i] = 0;
}
__global__ void hist_kernel(const int* __restrict__ dst) {
    int i = blockIdx.x * blockDim.x + threadIdx.x;
    if (i < N_EDGES) atomicAdd(&g_rowptr[dst[i] + 1], 1);
}
__global__ void scan_block_kernel() {
    __shared__ int s[1024];
    const int n = N_NODES + 1;
    int t = threadIdx.x;
    int gid = blockIdx.x * 1024 + t;
    s[t] = (gid < n) ? g_rowptr[gid] : 0;
    __syncthreads();
    #pragma unroll
    for (int off = 1; off < 1024; off <<= 1) {
        int v = (t >= off) ? s[t - off] : 0;
        __syncthreads();
        s[t] += v;
        __syncthreads();
    }
    if (gid < n) g_rowptr[gid] = s[t];
    if (t == 1023) g_bsums[blockIdx.x] = s[1023];
}
__global__ void scan_sums_kernel(int nb) {
    int acc = 0;
    for (int i = 0; i < nb; ++i) { int v = g_bsums[i]; g_bsums[i] = acc; acc += v; }
}
__global__ void scan_add_kernel() {
    const int n = N_NODES + 1;
    int gid = blockIdx.x * 1024 + threadIdx.x;
    if (gid < n) {
        int v = g_rowptr[gid] + g_bsums[blockIdx.x];
        g_rowptr[gid] = v;
        if (gid < N_NODES) g_cursor[gid] = v;
    }
}
__global__ void scatter_kernel(const int* __restrict__ src, const int* __restrict__ dst) {
    int i = blockIdx.x * blockDim.x + threadIdx.x;
    if (i < N_EDGES) {
        int d = dst[i];
        int pos = atomicAdd(&g_cursor[d], 1);
        g_col[pos] = src[i];
    }
}

// ================= weight transpose + bf16 hi/lo split =================
// B f32 [K,128] row-major  ->  bhi/blo bf16 [128][K] (K-major)
__global__ void conv_b_kernel(const float* __restrict__ B, __nv_bfloat16* __restrict__ bhi,
                              __nv_bfloat16* __restrict__ blo, int K) {
    int i = blockIdx.x * blockDim.x + threadIdx.x;
    if (i >= K * 128) return;
    int k = i >> 7, n = i & 127;
    float v = B[(size_t)k * 128 + n];
    __nv_bfloat16 h = __float2bfloat16(v);
    __nv_bfloat16 l = __float2bfloat16(v - __bfloat162float(h));
    bhi[(size_t)n * K + k] = h;
    blo[(size_t)n * K + k] = l;
}

// ================= HMMA (mma.sync bf16) GEMM ==========================
// C[M,128] = A[M,K] @ W, A fp32 (split on the fly), W pre-split K-major.
// 3-term split product: Ah*Bh + Al*Bh + Ah*Bl  (~1e-6 rel accuracy).
// Block tile 128x128, 8 warps as 4(m) x 2(n), warp tile 32x64.
#define ASTRIDE 40   // bf16 elems per smem row (32 data + 8 pad) -> conflict-free ldmatrix

__device__ __forceinline__ uint32_t pack_bf2(float x, float y) {
    __nv_bfloat162 t = __floats2bfloat162_rn(x, y);
    return *reinterpret_cast<uint32_t*>(&t);
}
__device__ __forceinline__ uint32_t smem_addr_u32(const void* p) {
    return (uint32_t)__cvta_generic_to_shared(p);
}
__device__ __forceinline__ void ldsm_x4(uint32_t* r, uint32_t addr) {
    asm volatile("ldmatrix.sync.aligned.m8n8.x4.shared.b16 {%0,%1,%2,%3}, [%4];"
                 : "=r"(r[0]), "=r"(r[1]), "=r"(r[2]), "=r"(r[3]) : "r"(addr));
}
__device__ __forceinline__ void mma_bf16(float* d, const uint32_t* a, const uint32_t* b) {
    asm volatile(
        "mma.sync.aligned.m16n8k16.row.col.f32.bf16.bf16.f32 "
        "{%0,%1,%2,%3}, {%4,%5,%6,%7}, {%8,%9}, {%0,%1,%2,%3};"
        : "+f"(d[0]), "+f"(d[1]), "+f"(d[2]), "+f"(d[3])
        : "r"(a[0]), "r"(a[1]), "r"(a[2]), "r"(a[3]), "r"(b[0]), "r"(b[1]));
}

template<bool BIAS_RELU>
__global__ __launch_bounds__(256, 2)
void gemm_mma(const float* __restrict__ A, const __nv_bfloat16* __restrict__ Bhi,
              const __nv_bfloat16* __restrict__ Blo, const float* __restrict__ bias,
              float* __restrict__ C, int M, int K)
{
    __shared__ __align__(16) __nv_bfloat16 sAh[128 * ASTRIDE];
    __shared__ __align__(16) __nv_bfloat16 sAl[128 * ASTRIDE];
    __shared__ __align__(16) __nv_bfloat16 sBh[128 * ASTRIDE];
    __shared__ __align__(16) __nv_bfloat16 sBl[128 * ASTRIDE];

    const int tid  = threadIdx.x;
    const int wid  = tid >> 5, lane = tid & 31;
    const int wr   = wid >> 1, wc = wid & 1;     // warp 4x2 grid
    const int m0   = blockIdx.x * 128;

    // fill mapping: thread t -> row r, k-half kh (16 elems)
    const int r  = tid >> 1;
    const int kh = (tid & 1) * 16;
    const int grow = m0 + r;
    const bool valid = grow < M;

    float acc[2][8][4];
    #pragma unroll
    for (int mt = 0; mt < 2; ++mt)
        #pragma unroll
        for (int nt = 0; nt < 8; ++nt)
            #pragma unroll
            for (int j = 0; j < 4; ++j) acc[mt][nt][j] = 0.f;

    // precomputed ldmatrix smem byte addresses (element offsets * 2)
    const uint32_t aAh = smem_addr_u32(sAh);
    const uint32_t aAl = smem_addr_u32(sAl);
    const uint32_t aBh = smem_addr_u32(sBh);
    const uint32_t aBl = smem_addr_u32(sBl);
    const int a_row = wr * 32 + (lane & 15);
    const int a_kof = (lane >> 4) * 8;
    const int b_row = wc * 64 + (lane & 7) + ((lane >> 4) << 3);
    const int b_kof = ((lane >> 3) & 1) * 8;

    const int nkt = K >> 5;
    for (int kt = 0; kt < nkt; ++kt) {
        __syncthreads();
        // ---- fill A (fp32 -> bf16 hi/lo) ----
        {
            const float* ap = A + (size_t)grow * K + kt * 32 + kh;
            float4 f0, f1, f2, f3;
            if (valid) {
                f0 = *(const float4*)(ap + 0);
                f1 = *(const float4*)(ap + 4);
                f2 = *(const float4*)(ap + 8);
                f3 = *(const float4*)(ap + 12);
            } else {
                f0 = make_float4(0.f, 0.f, 0.f, 0.f);
                f1 = f0; f2 = f0; f3 = f0;
            }
            uint4 uh0, uh1, ul0, ul1;
            uh0.x = pack_bf2(f0.x, f0.y); uh0.y = pack_bf2(f0.z, f0.w);
            uh0.z = pack_bf2(f1.x, f1.y); uh0.w = pack_bf2(f1.z, f1.w);
            uh1.x = pack_bf2(f2.x, f2.y); uh1.y = pack_bf2(f2.z, f2.w);
            uh1.z = pack_bf2(f3.x, f3.y); uh1.w = pack_bf2(f3.z, f3.w);
            const __nv_bfloat162* hp0 = (const __nv_bfloat162*)&uh0;
            const __nv_bfloat162* hp1 = (const __nv_bfloat162*)&uh1;
            float2 h;
            h = __bfloat1622float2(hp0[0]); ul0.x = pack_bf2(f0.x - h.x, f0.y - h.y);
            h = __bfloat1622float2(hp0[1]); ul0.y = pack_bf2(f0.z - h.x, f0.w - h.y);
            h = __bfloat1622float2(hp0[2]); ul0.z = pack_bf2(f1.x - h.x, f1.y - h.y);
            h = __bfloat1622float2(hp0[3]); ul0.w = pack_bf2(f1.z - h.x, f1.w - h.y);
            h = __bfloat1622float2(hp1[0]); ul1.x = pack_bf2(f2.x - h.x, f2.y - h.y);
            h = __bfloat1622float2(hp1[1]); ul1.y = pack_bf2(f2.z - h.x, f2.w - h.y);
            h = __bfloat1622float2(hp1[2]); ul1.z = pack_bf2(f3.x - h.x, f3.y - h.y);
            h = __bfloat1622float2(hp1[3]); ul1.w = pack_bf2(f3.z - h.x, f3.w - h.y);
            *(uint4*)&sAh[r * ASTRIDE + kh]     = uh0;
            *(uint4*)&sAh[r * ASTRIDE + kh + 8] = uh1;
            *(uint4*)&sAl[r * ASTRIDE + kh]     = ul0;
            *(uint4*)&sAl[r * ASTRIDE + kh + 8] = ul1;
        }
        // ---- fill B (pre-split bf16, K-major) ----
        {
            const __nv_bfloat16* bh = Bhi + (size_t)r * K + kt * 32 + kh;
            const __nv_bfloat16* bl = Blo + (size_t)r * K + kt * 32 + kh;
            *(uint4*)&sBh[r * ASTRIDE + kh]     = *(const uint4*)(bh + 0);
            *(uint4*)&sBh[r * ASTRIDE + kh + 8] = *(const uint4*)(bh + 8);
            *(uint4*)&sBl[r * ASTRIDE + kh]     = *(const uint4*)(bl + 0);
            *(uint4*)&sBl[r * ASTRIDE + kh + 8] = *(const uint4*)(bl + 8);
        }
        __syncthreads();

        #pragma unroll
        for (int ks = 0; ks < 2; ++ks) {
            const uint32_t aoff = (uint32_t)((a_row * ASTRIDE + ks * 16 + a_kof) * 2);
            const uint32_t boff = (uint32_t)((b_row * ASTRIDE + ks * 16 + b_kof) * 2);
            uint32_t ah[2][4], al[2][4], bb[8][2];
            ldsm_x4(ah[0], aAh + aoff);
            ldsm_x4(ah[1], aAh + aoff + 16 * ASTRIDE * 2);
            ldsm_x4(al[0], aAl + aoff);
            ldsm_x4(al[1], aAl + aoff + 16 * ASTRIDE * 2);
            #pragma unroll
            for (int p = 0; p < 4; ++p)
                ldsm_x4(&bb[p * 2][0], aBh + boff + (uint32_t)(p * 16 * ASTRIDE * 2));
            #pragma unroll
            for (int mt = 0; mt < 2; ++mt)
                #pragma unroll
                for (int nt = 0; nt < 8; ++nt) {
                    mma_bf16(acc[mt][nt], ah[mt], bb[nt]);
                    mma_bf16(acc[mt][nt], al[mt], bb[nt]);
                }
            #pragma unroll
            for (int p = 0; p < 4; ++p)
                ldsm_x4(&bb[p * 2][0], aBl + boff + (uint32_t)(p * 16 * ASTRIDE * 2));
            #pragma unroll
            for (int mt = 0; mt < 2; ++mt)
                #pragma unroll
                for (int nt = 0; nt < 8; ++nt)
                    mma_bf16(acc[mt][nt], ah[mt], bb[nt]);
        }
    }

    // ---- epilogue ----
    const int colb = wc * 64 + (lane & 3) * 2;
    const int rowb = m0 + wr * 32 + (lane >> 2);
    #pragma unroll
    for (int mt = 0; mt < 2; ++mt) {
        #pragma unroll
        for (int nt = 0; nt < 8; ++nt) {
            int col = colb + nt * 8;
            float2 v0, v1;
            v0.x = acc[mt][nt][0]; v0.y = acc[mt][nt][1];
            v1.x = acc[mt][nt][2]; v1.y = acc[mt][nt][3];
            if (BIAS_RELU) {
                v0.x = fmaxf(v0.x + __ldg(&bias[col]),     0.f);
                v0.y = fmaxf(v0.y + __ldg(&bias[col + 1]), 0.f);
                v1.x = fmaxf(v1.x + __ldg(&bias[col]),     0.f);
                v1.y = fmaxf(v1.y + __ldg(&bias[col + 1]), 0.f);
            }
            int row0 = rowb + mt * 16;
            int row1 = row0 + 8;
            if (row0 < M) *(float2*)&C[(size_t)row0 * 128 + col] = v0;
            if (row1 < M) *(float2*)&C[(size_t)row1 * 128 + col] = v1;
        }
    }
}

// ================= attention logits =================
__global__ void al_kernel(const float* __restrict__ xh,
                          const float* __restrict__ att_s,
                          const float* __restrict__ att_d)
{
    int idx = blockIdx.x * blockDim.x + threadIdx.x;
    if (idx >= N_NODES * NHEAD) return;
    int n = idx >> 3, hd = idx & 7;
    const float* xp = xh + (size_t)n * HID + hd * CH;
    const float* as = att_s + hd * CH;
    const float* ad = att_d + hd * CH;
    float ss = 0.f, dd = 0.f;
    #pragma unroll
    for (int c = 0; c < CH; c += 4) {
        float4 v = *(const float4*)(xp + c);
        float4 a = *(const float4*)(as + c);
        float4 b = *(const float4*)(ad + c);
        ss += v.x * a.x + v.y * a.y + v.z * a.z + v.w * a.w;
        dd += v.x * b.x + v.y * b.y + v.z * b.z + v.w * b.w;
    }
    g_als[idx] = ss;
    g_ald[idx] = dd;
}

// ================= GAT aggregation (warp per dst) =================
__global__ __launch_bounds__(256)
void gat_aggregate(const float* __restrict__ xh,
                   const float* __restrict__ gat_b,
                   const float* __restrict__ ln_g,
                   const float* __restrict__ ln_b,
                   float* __restrict__ h)
{
    int w = (blockIdx.x * blockDim.x + threadIdx.x) >> 5;
    if (w >= N_NODES) return;
    int lane = threadIdx.x & 31;
    int hd = lane >> 2;
    int f = lane * 4;

    float a_d = g_ald[w * NHEAD + hd];
    float e0 = g_als[w * NHEAD + hd] + a_d;
    e0 = fmaxf(e0, 0.2f * e0);
    float m = e0;
    float denom = 1.0f;
    float4 acc = *(const float4*)&xh[(size_t)w * HID + f];

    int beg = g_rowptr[w], end = g_rowptr[w + 1];
    for (int i = beg; i < end; ++i) {
        int s = g_col[i];
        float e2 = g_als[s * NHEAD + hd] + a_d;
        e2 = fmaxf(e2, 0.2f * e2);
        float mn = fmaxf(m, e2);
        float sc = __expf(m - mn);
        float p  = __expf(e2 - mn);
        float4 v = *(const float4*)&xh[(size_t)s * HID + f];
        acc.x = acc.x * sc + p * v.x;
        acc.y = acc.y * sc + p * v.y;
        acc.z = acc.z * sc + p * v.z;
        acc.w = acc.w * sc + p * v.w;
        denom = denom * sc + p;
        m = mn;
    }

    float inv = 1.0f / denom;
    float4 r  = *(const float4*)&h[(size_t)w * HID + f];
    float4 gb = *(const float4*)&gat_b[f];
    float v0 = fmaf(acc.x, inv, gb.x + r.x);
    float v1 = fmaf(acc.y, inv, gb.y + r.y);
    float v2 = fmaf(acc.z, inv, gb.z + r.z);
    float v3 = fmaf(acc.w, inv, gb.w + r.w);

    float sum = v0 + v1 + v2 + v3;
    float sq  = v0 * v0 + v1 * v1 + v2 * v2 + v3 * v3;
    #pragma unroll
    for (int off = 16; off; off >>= 1) {
        sum += __shfl_xor_sync(0xffffffffu, sum, off);
        sq  += __shfl_xor_sync(0xffffffffu, sq,  off);
    }
    float mean = sum * (1.0f / 128.0f);
    float var  = sq  * (1.0f / 128.0f) - mean * mean;
    float rs = rsqrtf(var + 1e-5f);

    float4 g4 = *(const float4*)&ln_g[f];
    float4 b4 = *(const float4*)&ln_b[f];
    float4 o;
    o.x = fmaxf((v0 - mean) * rs * g4.x + b4.x, 0.f);
    o.y = fmaxf((v1 - mean) * rs * g4.y + b4.y, 0.f);
    o.z = fmaxf((v2 - mean) * rs * g4.z + b4.z, 0.f);
    o.w = fmaxf((v3 - mean) * rs * g4.w + b4.w, 0.f);
    *(float4*)&h[(size_t)w * HID + f] = o;
}

// ================= classifier + log_softmax =================
__global__ __launch_bounds__(256)
void classifier_kernel(const float* __restrict__ h,
                       const float* __restrict__ w1, const float* __restrict__ b1,
                       const float* __restrict__ w2, const float* __restrict__ b2,
                       float* __restrict__ out)
{
    __shared__ __align__(16) float s_w1[HID * 64];
    __shared__ __align__(16) float s_w2[64 * OUT_DIM];
    __shared__ float s_b1[64];
    __shared__ float s_b2[OUT_DIM];
    __shared__ __align__(16) float s_h[8][HID];
    __shared__ float s_hid[8][64];

    int tid = threadIdx.x;
    for (int i = tid; i < HID * 64; i += 256) s_w1[i] = w1[i];
    for (int i = tid; i < 64 * OUT_DIM; i += 256) s_w2[i] = w2[i];
    if (tid < 64) s_b1[tid] = b1[tid];
    if (tid < OUT_DIM) s_b2[tid] = b2[tid];
    __syncthreads();

    int warp = tid >> 5, lane = tid & 31;
    int stride = gridDim.x * 8;
    for (int row = blockIdx.x * 8 + warp; row < N_NODES; row += stride) {
        *(float4*)&s_h[warp][lane * 4] = *(const float4*)&h[(size_t)row * HID + lane * 4];
        __syncwarp();
        float acc0 = 0.f, acc1 = 0.f;
        #pragma unroll 8
        for (int k = 0; k < HID; ++k) {
            float x = s_h[warp][k];
            acc0 = fmaf(x, s_w1[k * 64 + lane], acc0);
            acc1 = fmaf(x, s_w1[k * 64 + lane + 32], acc1);
        }
        acc0 = fmaxf(acc0 + s_b1[lane], 0.f);
        acc1 = fmaxf(acc1 + s_b1[lane + 32], 0.f);
        s_hid[warp][lane] = acc0;
        s_hid[warp][lane + 32] = acc1;
        __syncwarp();
        int o = lane & 15;
        int kbase = (lane >> 4) * 32;
        float part = 0.f;
        #pragma unroll 8
        for (int k = 0; k < 32; ++k)
            part = fmaf(s_hid[warp][kbase + k], s_w2[(kbase + k) * OUT_DIM + o], part);
        part += __shfl_xor_sync(0xffffffffu, part, 16);
        float logit = part + s_b2[o];
        float mx = logit;
        #pragma unroll
        for (int off = 8; off; off >>= 1)
            mx = fmaxf(mx, __shfl_xor_sync(0xffffffffu, mx, off));
        float ex = __expf(logit - mx);
        float sm = ex;
        #pragma unroll
        for (int off = 8; off; off >>= 1)
            sm += __shfl_xor_sync(0xffffffffu, sm, off);
        float res = logit - mx - logf(sm);
        if (lane < 16) out[(size_t)row * OUT_DIM + lane] = res;
        __syncwarp();
    }
}

// ================= launch =================
extern "C" void kernel_launch(void* const* d_in, const int* in_sizes, int n_in,
                              void* d_out, int out_size)
{
    const float* x       = (const float*)d_in[0];
    const int*   ei      = (const int*)  d_in[1];
    const float* proj_w  = (const float*)d_in[2];
    const float* proj_b  = (const float*)d_in[3];
    const float* lin_w   = (const float*)d_in[4];
    const float* att_src = (const float*)d_in[5];
    const float* att_dst = (const float*)d_in[6];
    const float* gat_b   = (const float*)d_in[7];
    const float* ln_g    = (const float*)d_in[8];
    const float* ln_b    = (const float*)d_in[9];
    const float* cls_w1  = (const float*)d_in[10];
    const float* cls_b1  = (const float*)d_in[11];
    const float* cls_w2  = (const float*)d_in[12];
    const float* cls_b2  = (const float*)d_in[13];
    float* out = (float*)d_out;

    const int* src = ei;
    const int* dst = ei + N_EDGES;

    float *h_ptr = nullptr, *xh_ptr = nullptr;
    __nv_bfloat16 *bhi = nullptr, *blo = nullptr;
    cudaGetSymbolAddress((void**)&h_ptr, g_h);
    cudaGetSymbolAddress((void**)&xh_ptr, g_xh);
    cudaGetSymbolAddress((void**)&bhi, g_bhi);
    cudaGetSymbolAddress((void**)&blo, g_blo);

    const int SCAN_BLOCKS = (N_NODES + 1 + 1023) / 1024;  // 49

    // --- CSR build (graph static across layers) ---
    zero_rowptr_kernel<<<(N_NODES + 1 + 255) / 256, 256>>>();
    hist_kernel<<<(N_EDGES + 255) / 256, 256>>>(dst);
    scan_block_kernel<<<SCAN_BLOCKS, 1024>>>();
    scan_sums_kernel<<<1, 1>>>(SCAN_BLOCKS);
    scan_add_kernel<<<SCAN_BLOCKS, 1024>>>();
    scatter_kernel<<<(N_EDGES + 255) / 256, 256>>>(src, dst);

    // --- weight transpose + split (tiny) ---
    conv_b_kernel<<<(IN_DIM * 128 + 255) / 256, 256>>>(proj_w, bhi + B_PROJ_OFF, blo + B_PROJ_OFF, IN_DIM);
    for (int l = 0; l < NLAYER; ++l)
        conv_b_kernel<<<(HID * 128 + 255) / 256, 256>>>(lin_w + (size_t)l * HID * HID,
            bhi + B_LIN_OFF + l * 128 * HID, blo + B_LIN_OFF + l * 128 * HID, HID);

    const int GEMM_GRID = (N_NODES + 127) / 128;  // 391

    // --- projection: h = relu(x @ proj_w + proj_b) ---
    gemm_mma<true><<<GEMM_GRID, 256>>>(
        x, bhi + B_PROJ_OFF, blo + B_PROJ_OFF, proj_b, h_ptr, N_NODES, IN_DIM);

    // --- GAT layers ---
    for (int l = 0; l < NLAYER; ++l) {
        gemm_mma<false><<<GEMM_GRID, 256>>>(
            h_ptr, bhi + B_LIN_OFF + l * 128 * HID, blo + B_LIN_OFF + l * 128 * HID,
            nullptr, xh_ptr, N_NODES, HID);
        al_kernel<<<(N_NODES * NHEAD + 255) / 256, 256>>>(
            xh_ptr, att_src + l * NHEAD * CH, att_dst + l * NHEAD * CH);
        gat_aggregate<<<N_NODES / 8, 256>>>(
            xh_ptr, gat_b + l * HID, ln_g + l * HID, ln_b + l * HID, h_ptr);
    }

    // --- classifier + log_softmax ---
    classifier_kernel<<<592, 256>>>(h_ptr, cls_w1, cls_b1, cls_w2, cls_b2, out);
}